// round 6
// baseline (speedup 1.0000x reference)
#include <cuda_runtime.h>
#include <mma.h>
#include <cstdint>

namespace wm = nvcuda::wmma;

#define BB   4
#define DIN_ 256
#define SS   2048
#define DMM  512
#define HH   8
#define DKK  64
#define NH   32                      // B*H
#define ZSIZE (BB*DIN_*SS)           // 2097152

// Scratch (device globals: allocation-free rule)
__device__ float g_Q[NH*SS*DKK];     // [n][s][dk]
__device__ float g_K[NH*SS*DKK];
__device__ float g_V[NH*SS*DKK];
__device__ float g_AO[SS*NH*DKK];    // flat [S][B*H][dk] == [B*S][DM] view

__device__ __forceinline__ float f2tf32(float x){
    float r; asm("cvt.rna.tf32.f32 %0, %1;" : "=f"(r) : "f"(x)); return r;
}

using FragA  = wm::fragment<wm::matrix_a,    16,16,8, wm::precision::tf32, wm::row_major>;
using FragBc = wm::fragment<wm::matrix_b,    16,16,8, wm::precision::tf32, wm::col_major>;
using FragBr = wm::fragment<wm::matrix_b,    16,16,8, wm::precision::tf32, wm::row_major>;
using FragC  = wm::fragment<wm::accumulator, 16,16,8, float>;

template<class F>
__device__ __forceinline__ void split_frag(const F& raw, F& hi, F& lo){
#pragma unroll
    for (int i = 0; i < raw.num_elements; i++){
        float h = f2tf32(raw.x[i]);
        hi.x[i] = h;
        lo.x[i] = f2tf32(raw.x[i] - h);
    }
}

// ---------------------------------------------------------------------------
// Kernel 1: QKV projections.  C[r,m] = sum_i xt[r,i]*W[m,i] + b[m]
//   rows r = s*4 + b  (xt = x transposed [S,B,DIN]);  split-3 tf32.
//   Output scattered to per-head layout [n= b*H + m/64][s][m%64].
// grid (128 row-tiles, 4 col-tiles, 3={Q,K,V}), 256 threads.
// ---------------------------------------------------------------------------
__global__ void __launch_bounds__(256) qkv_kernel(
        const float* __restrict__ x,
        const float* __restrict__ Wq, const float* __restrict__ bq,
        const float* __restrict__ Wk, const float* __restrict__ bk,
        const float* __restrict__ Wv, const float* __restrict__ bv)
{
    __shared__ __align__(128) float sbuf[64*132];   // A-tile (64x36) / C-tile (64x132)

    const int which = blockIdx.z;
    const float* W    = (which==0) ? Wq : (which==1 ? Wk : Wv);
    const float* bias = (which==0) ? bq : (which==1 ? bk : bv);
    float* out        = (which==0) ? g_Q : (which==1 ? g_K : g_V);

    const int r0 = blockIdx.x * 64;       // row tile: rows r = s*4+b
    const int m0 = blockIdx.y * 128;      // output column tile
    const int s0 = r0 >> 2;
    const int t  = threadIdx.x;
    const int w  = t >> 5;
    const int wm = w >> 2;                // 0..1  (32 rows each)
    const int wn = w & 3;                 // 0..3  (32 cols each)

    FragC acc[2][2];
#pragma unroll
    for (int a=0;a<2;a++)
#pragma unroll
        for (int b2=0;b2<2;b2++) wm::fill_fragment(acc[a][b2], 0.0f);

    for (int kc = 0; kc < DIN_; kc += 32){
        // stage A tile 64 rows x 32 i  (gather-transpose of x)
#pragma unroll
        for (int j = 0; j < 8; j++){
            int idx = j*256 + t;                   // 0..2047
            int sl  = idx & 15;                    // s within tile
            int p   = idx >> 4;                    // 0..127 -> (b, i)
            int bb  = p & 3;
            int il  = p >> 2;                      // 0..31
            sbuf[(sl*4 + bb)*36 + il] = x[bb*(DIN_*SS) + (kc+il)*SS + (s0+sl)];
        }
        __syncthreads();

#pragma unroll
        for (int ks = 0; ks < 4; ks++){
            FragA ahi[2], alo[2];
#pragma unroll
            for (int mt = 0; mt < 2; mt++){
                FragA araw;
                wm::load_matrix_sync(araw, sbuf + (wm*32 + mt*16)*36 + ks*8, 36);
                split_frag(araw, ahi[mt], alo[mt]);
            }
#pragma unroll
            for (int nt = 0; nt < 2; nt++){
                FragBc braw, bhi, blo;
                wm::load_matrix_sync(braw, W + (m0 + wn*32 + nt*16)*DIN_ + kc + ks*8, DIN_);
                split_frag(braw, bhi, blo);
#pragma unroll
                for (int mt = 0; mt < 2; mt++){
                    wm::mma_sync(acc[mt][nt], ahi[mt], bhi, acc[mt][nt]);
                    wm::mma_sync(acc[mt][nt], ahi[mt], blo, acc[mt][nt]);
                    wm::mma_sync(acc[mt][nt], alo[mt], bhi, acc[mt][nt]);
                }
            }
        }
        __syncthreads();
    }

    // epilogue: C tile -> smem row-major [64][132], then scatter to head layout
#pragma unroll
    for (int mt = 0; mt < 2; mt++)
#pragma unroll
        for (int nt = 0; nt < 2; nt++)
            wm::store_matrix_sync(sbuf + (wm*32 + mt*16)*132 + wn*32 + nt*16,
                                  acc[mt][nt], 132, wm::mem_row_major);
    __syncthreads();

    for (int it = 0; it < 32; it++){
        int rl = it*2 + (t >> 7);              // 0..63
        int ml = t & 127;                      // 0..127
        int m  = m0 + ml;
        float v = sbuf[rl*132 + ml] + bias[m];
        int s  = s0 + (rl >> 2);
        int bb = rl & 3;
        int h  = m >> 6;
        int d  = m & 63;
        out[((bb*HH + h)*SS + s)*DKK + d] = v;
    }
}

// ---------------------------------------------------------------------------
// Kernel 2: attention.  CTA = (head n, 16 q-rows).
//   Phase A: scores[16][2048] = Q Kᵀ (split-3 tf32) into smem fp32.
//   Phase B: per-row max, in-place exp, rowsum; write attn_w = e/sum to d_out.
//   Phase C: PV (split-3 tf32) on unnormalized e, scale by 1/sum, store g_AO.
// grid (128 q-tiles, 32 heads), 256 threads, ~140KB dyn smem.
// ---------------------------------------------------------------------------
__global__ void __launch_bounds__(256) attn_kernel(float* __restrict__ d_out)
{
    extern __shared__ __align__(128) float smem[];
    float* sc   = smem;                     // [16][2056] fp32 scores / e
    float* pvb  = smem + 16*2056;           // [8][16][16] PV partials
    float* sinv = pvb + 8*256;              // [16]

    const int n    = blockIdx.y;
    const int q0   = blockIdx.x * 16;
    const int t    = threadIdx.x;
    const int w    = t >> 5;
    const int lane = t & 31;

    const float* Qp = g_Q + (n*SS + q0)*DKK;
    const float* Kp = g_K + n*SS*DKK;
    const float* Vp = g_V + n*SS*DKK;

    // preload Q fragments for all 8 d-chunks (hi/lo)
    FragA ahi[8], alo[8];
#pragma unroll
    for (int dc = 0; dc < 8; dc++){
        FragA araw;
        wm::load_matrix_sync(araw, Qp + dc*8, DKK);
        split_frag(araw, ahi[dc], alo[dc]);
    }

    // ---- Phase A: each warp computes scores for keys [w*256, w*256+256)
    for (int kt = 0; kt < 16; kt++){
        int key0 = w*256 + kt*16;
        FragC acc; wm::fill_fragment(acc, 0.0f);
#pragma unroll
        for (int dc = 0; dc < 8; dc++){
            FragBc braw, bhi, blo;
            wm::load_matrix_sync(braw, Kp + key0*DKK + dc*8, DKK);  // Kᵀ col-major view
            split_frag(braw, bhi, blo);
            wm::mma_sync(acc, ahi[dc], bhi, acc);
            wm::mma_sync(acc, ahi[dc], blo, acc);
            wm::mma_sync(acc, alo[dc], bhi, acc);
        }
        wm::store_matrix_sync(sc + key0, acc, 2056, wm::mem_row_major);
    }
    __syncthreads();

    // ---- Phase B: softmax rows 2w, 2w+1 (in-place exp) + attn_w write
#pragma unroll
    for (int j = 0; j < 2; j++){
        int r = w*2 + j;
        float* row = sc + r*2056;
        float m = -3.4e38f;
        for (int c = lane; c < SS; c += 32) m = fmaxf(m, row[c]);
#pragma unroll
        for (int o = 16; o > 0; o >>= 1) m = fmaxf(m, __shfl_xor_sync(0xffffffffu, m, o));
        float sum = 0.f;
        for (int c = lane; c < SS; c += 32){
            float e = __expf(row[c] - m);
            row[c] = e;
            sum += e;
        }
#pragma unroll
        for (int o = 16; o > 0; o >>= 1) sum += __shfl_xor_sync(0xffffffffu, sum, o);
        float inv = 1.0f / sum;
        if (lane == 0) sinv[r] = inv;
        float* ow = d_out + (size_t)ZSIZE + (size_t)n*SS*SS + (size_t)(q0 + r)*SS;
        for (int c = lane; c < SS; c += 32) ow[c] = row[c] * inv;
    }
    __syncthreads();

    // ---- Phase C: PV.  warp -> (key half, d-tile); split-3 tf32.
    {
        int half = w >> 2;       // keys 0..1023 / 1024..2047
        int nt   = w & 3;        // d-tile 16
        FragC acc; wm::fill_fragment(acc, 0.0f);
        for (int ks = 0; ks < 128; ks++){
            int k0 = half*1024 + ks*8;
            FragA araw, phi, plo;
            wm::load_matrix_sync(araw, sc + k0, 2056);
            split_frag(araw, phi, plo);
            FragBr braw, vhi, vlo;
            wm::load_matrix_sync(braw, Vp + k0*DKK + nt*16, DKK);
            split_frag(braw, vhi, vlo);
            wm::mma_sync(acc, phi, vhi, acc);
            wm::mma_sync(acc, phi, vlo, acc);
            wm::mma_sync(acc, plo, vhi, acc);
        }
        wm::store_matrix_sync(pvb + w*256, acc, 16, wm::mem_row_major);
    }
    __syncthreads();

    // reduce the two key-halves, scale by 1/sum, store flat [q][n][d]
    {
        int q  = t >> 4;          // 0..15
        int db = (t & 15) * 4;    // 0..60
        float inv = sinv[q];
#pragma unroll
        for (int u = 0; u < 4; u++){
            int d  = db + u;
            int nt = d >> 4;
            float v = (pvb[nt*256 + q*16 + (d & 15)] +
                       pvb[(nt+4)*256 + q*16 + (d & 15)]) * inv;
            g_AO[(size_t)(q0 + q)*(NH*DKK) + n*DKK + d] = v;
        }
    }
}

// ---------------------------------------------------------------------------
// Kernel 3: out-projection + output transpose.
//   A = g_AO viewed [8192][512] (row r = b*2048+s), B = Wo (col-major view),
//   Z[b][e][s] = C[r][e] + bo[e].  split-3 tf32.
// grid (64 row-tiles, 4 col-tiles), 256 threads.
// ---------------------------------------------------------------------------
__global__ void __launch_bounds__(256) oproj_kernel(
        const float* __restrict__ Wo, const float* __restrict__ bo,
        float* __restrict__ d_out)
{
    __shared__ __align__(128) float sbuf[64*132];   // C stored col-major [e][r]

    const int r0 = blockIdx.x * 128;
    const int e0 = blockIdx.y * 64;
    const int t  = threadIdx.x;
    const int w  = t >> 5;
    const int wmw = w >> 1;     // 0..3 (32 rows each)
    const int wnw = w & 1;      // 0..1 (32 cols each)

    FragC acc[2][2];
#pragma unroll
    for (int a=0;a<2;a++)
#pragma unroll
        for (int b2=0;b2<2;b2++) wm::fill_fragment(acc[a][b2], 0.0f);

    for (int ks = 0; ks < 64; ks++){
        FragA ahi[2], alo[2];
#pragma unroll
        for (int mt = 0; mt < 2; mt++){
            FragA araw;
            wm::load_matrix_sync(araw, g_AO + (size_t)(r0 + wmw*32 + mt*16)*DMM + ks*8, DMM);
            split_frag(araw, ahi[mt], alo[mt]);
        }
#pragma unroll
        for (int nt = 0; nt < 2; nt++){
            FragBc braw, bhi, blo;
            wm::load_matrix_sync(braw, Wo + (e0 + wnw*32 + nt*16)*DMM + ks*8, DMM);
            split_frag(braw, bhi, blo);
#pragma unroll
            for (int mt = 0; mt < 2; mt++){
                wm::mma_sync(acc[mt][nt], ahi[mt], bhi, acc[mt][nt]);
                wm::mma_sync(acc[mt][nt], ahi[mt], blo, acc[mt][nt]);
                wm::mma_sync(acc[mt][nt], alo[mt], bhi, acc[mt][nt]);
            }
        }
    }

    // store C transposed (col-major): sbuf[e_loc*132 + r_loc]
#pragma unroll
    for (int mt = 0; mt < 2; mt++)
#pragma unroll
        for (int nt = 0; nt < 2; nt++)
            wm::store_matrix_sync(sbuf + (wnw*32 + nt*16)*132 + wmw*32 + mt*16,
                                  acc[mt][nt], 132, wm::mem_col_major);
    __syncthreads();

    const int b  = r0 >> 11;
    const int s0 = r0 & 2047;
    for (int it = 0; it < 32; it++){
        int el = it*2 + (t >> 7);     // 0..63
        int sl = t & 127;             // 0..127
        float v = sbuf[el*132 + sl] + bo[e0 + el];
        d_out[(size_t)b*(DIN_*SS) + (size_t)(e0 + el)*SS + s0 + sl] = v;
    }
}

// ---------------------------------------------------------------------------
extern "C" void kernel_launch(void* const* d_in, const int* in_sizes, int n_in,
                              void* d_out, int out_size)
{
    const float* x  = (const float*)d_in[0];
    const float* Wq = (const float*)d_in[1];
    const float* bq = (const float*)d_in[2];
    const float* Wk = (const float*)d_in[3];
    const float* bk = (const float*)d_in[4];
    const float* Wv = (const float*)d_in[5];
    const float* bv = (const float*)d_in[6];
    const float* Wo = (const float*)d_in[7];
    const float* bo = (const float*)d_in[8];
    float* out = (float*)d_out;

    const int attn_smem = (16*2056 + 8*256 + 16) * 4;   // 139,840 B
    cudaFuncSetAttribute(attn_kernel, cudaFuncAttributeMaxDynamicSharedMemorySize, attn_smem);

    qkv_kernel<<<dim3(128, 4, 3), 256>>>(x, Wq, bq, Wk, bk, Wv, bv);
    attn_kernel<<<dim3(128, 32), 256, attn_smem>>>(out);
    oproj_kernel<<<dim3(64, 4), 256>>>(Wo, bo, out);
}

// round 7
// speedup vs baseline: 1.1339x; 1.1339x over previous
#include <cuda_runtime.h>
#include <mma.h>
#include <cstdint>

namespace wm = nvcuda::wmma;

#define BB   4
#define DIN_ 256
#define SS   2048
#define DMM  512
#define HH   8
#define DKK  64
#define NH   32                      // B*H
#define ZSIZE (BB*DIN_*SS)           // 2097152

// ---- device-global scratch (allocation-free rule) -------------------------
__device__ float g_Qh[NH*SS*DKK], g_Ql[NH*SS*DKK];
__device__ float g_Kh[NH*SS*DKK], g_Kl[NH*SS*DKK];
__device__ float g_Vh[NH*SS*DKK], g_Vl[NH*SS*DKK];
__device__ float g_AOh[SS*NH*DKK], g_AOl[SS*NH*DKK];   // flat [S][B*H][dk]
__device__ float g_Wqh[DMM*DIN_], g_Wql[DMM*DIN_];
__device__ float g_Wkh[DMM*DIN_], g_Wkl[DMM*DIN_];
__device__ float g_Wvh[DMM*DIN_], g_Wvl[DMM*DIN_];
__device__ float g_Woh[DIN_*DMM], g_Wol[DIN_*DMM];

__device__ __forceinline__ float f2tf32(float x){
    float r; asm("cvt.rna.tf32.f32 %0, %1;" : "=f"(r) : "f"(x)); return r;
}

using FragA  = wm::fragment<wm::matrix_a,    16,16,8, wm::precision::tf32, wm::row_major>;
using FragBc = wm::fragment<wm::matrix_b,    16,16,8, wm::precision::tf32, wm::col_major>;
using FragBr = wm::fragment<wm::matrix_b,    16,16,8, wm::precision::tf32, wm::row_major>;
using FragC  = wm::fragment<wm::accumulator, 16,16,8, float>;

// ---------------------------------------------------------------------------
// Kernel 0: split weights into tf32 hi/lo once.
// ---------------------------------------------------------------------------
__global__ void split_w_kernel(const float* __restrict__ s,
                               float* __restrict__ h, float* __restrict__ l, int n)
{
    int i = blockIdx.x * 256 + threadIdx.x;
    if (i < n){ float v = s[i]; float hh = f2tf32(v); h[i] = hh; l[i] = v - hh; }
}

// ---------------------------------------------------------------------------
// Kernel 1: QKV projections with pre-split W; A tile split at staging time.
//   Output: per-head hi/lo arrays [n][s][64].
// grid (128 row-tiles, 4 col-tiles, 3={Q,K,V}), 256 threads.
// ---------------------------------------------------------------------------
__global__ void __launch_bounds__(256) qkv_kernel(
        const float* __restrict__ x,
        const float* __restrict__ bq, const float* __restrict__ bk,
        const float* __restrict__ bv)
{
    __shared__ __align__(128) float sbuf[9216];   // 2x (64x36) A hi/lo, or 64x132 C
    float* shi = sbuf;
    float* slo = sbuf + 64*36;

    const int which = blockIdx.z;
    const float* Wh   = (which==0) ? g_Wqh : (which==1 ? g_Wkh : g_Wvh);
    const float* Wl   = (which==0) ? g_Wql : (which==1 ? g_Wkl : g_Wvl);
    const float* bias = (which==0) ? bq   : (which==1 ? bk   : bv);
    float* outh       = (which==0) ? g_Qh : (which==1 ? g_Kh : g_Vh);
    float* outl       = (which==0) ? g_Ql : (which==1 ? g_Kl : g_Vl);

    const int r0 = blockIdx.x * 64;       // rows r = s*4+b
    const int m0 = blockIdx.y * 128;
    const int s0 = r0 >> 2;
    const int t  = threadIdx.x;
    const int w  = t >> 5;
    const int wm = w >> 2;                // 0..1
    const int wn = w & 3;                 // 0..3

    FragC acc[2][2];
#pragma unroll
    for (int a=0;a<2;a++)
#pragma unroll
        for (int b2=0;b2<2;b2++) wm::fill_fragment(acc[a][b2], 0.0f);

    for (int kc = 0; kc < DIN_; kc += 32){
#pragma unroll
        for (int j = 0; j < 8; j++){
            int idx = j*256 + t;
            int sl  = idx & 15;
            int p   = idx >> 4;
            int bb  = p & 3;
            int il  = p >> 2;
            float v = x[bb*(DIN_*SS) + (kc+il)*SS + (s0+sl)];
            float h = f2tf32(v);
            int pos = (sl*4 + bb)*36 + il;
            shi[pos] = h;
            slo[pos] = v - h;
        }
        __syncthreads();

#pragma unroll
        for (int ks = 0; ks < 4; ks++){
            FragA ahi[2], alo[2];
#pragma unroll
            for (int mt = 0; mt < 2; mt++){
                wm::load_matrix_sync(ahi[mt], shi + (wm*32 + mt*16)*36 + ks*8, 36);
                wm::load_matrix_sync(alo[mt], slo + (wm*32 + mt*16)*36 + ks*8, 36);
            }
#pragma unroll
            for (int nt = 0; nt < 2; nt++){
                FragBc bhi, blo;
                const int wofs = (m0 + wn*32 + nt*16)*DIN_ + kc + ks*8;
                wm::load_matrix_sync(bhi, Wh + wofs, DIN_);
                wm::load_matrix_sync(blo, Wl + wofs, DIN_);
#pragma unroll
                for (int mt = 0; mt < 2; mt++){
                    wm::mma_sync(acc[mt][nt], ahi[mt], bhi, acc[mt][nt]);
                    wm::mma_sync(acc[mt][nt], ahi[mt], blo, acc[mt][nt]);
                    wm::mma_sync(acc[mt][nt], alo[mt], bhi, acc[mt][nt]);
                }
            }
        }
        __syncthreads();
    }

#pragma unroll
    for (int mt = 0; mt < 2; mt++)
#pragma unroll
        for (int nt = 0; nt < 2; nt++)
            wm::store_matrix_sync(sbuf + (wm*32 + mt*16)*132 + wn*32 + nt*16,
                                  acc[mt][nt], 132, wm::mem_row_major);
    __syncthreads();

    for (int it = 0; it < 32; it++){
        int rl = it*2 + (t >> 7);
        int ml = t & 127;
        int m  = m0 + ml;
        float v = sbuf[rl*132 + ml] + bias[m];
        int s  = s0 + (rl >> 2);
        int bb = rl & 3;
        int h  = m >> 6;
        int d  = m & 63;
        size_t o = (size_t)((bb*HH + h)*SS + s)*DKK + d;
        float hi = f2tf32(v);
        outh[o] = hi;
        outl[o] = v - hi;
    }
}

// ---------------------------------------------------------------------------
// Kernel 2: attention.  CTA = (head n, 16 q-rows), 512 threads (16 warps).
//   Phase A: scores via split-3 tf32 (pre-split Q/K), 2 accs per warp.
//   Phase B: softmax; write exact attn_w; round e to tf32 in-place.
//   Phase C: PV with exact-tf32 P x (Vh+Vl): 2 mma per k-step, 2 accs.
// grid (128 q-tiles, 32 heads), ~148KB dyn smem.
// ---------------------------------------------------------------------------
__global__ void __launch_bounds__(512) attn_kernel(float* __restrict__ d_out)
{
    extern __shared__ __align__(128) float smem[];
    float* sc   = smem;                     // [16][2056] scores / tf32-e
    float* pvb  = smem + 16*2056;           // [16][16][16] PV partials
    float* sinv = pvb + 16*256;             // [16]

    const int n    = blockIdx.y;
    const int q0   = blockIdx.x * 16;
    const int t    = threadIdx.x;
    const int w    = t >> 5;                // 0..15
    const int lane = t & 31;

    const size_t qofs = (size_t)(n*SS + q0)*DKK;
    const float* Khp = g_Kh + (size_t)n*SS*DKK;
    const float* Klp = g_Kl + (size_t)n*SS*DKK;
    const float* Vhp = g_Vh + (size_t)n*SS*DKK;
    const float* Vlp = g_Vl + (size_t)n*SS*DKK;

    // ---- Phase A: warp w -> keys [w*128, w*128+128), 2 tiles at a time
    {
        const int kb = w * 128;
#pragma unroll
        for (int p = 0; p < 4; p++){
            const int t0 = kb + p*32;
            const int t1 = t0 + 16;
            FragC a0, a1;
            wm::fill_fragment(a0, 0.0f);
            wm::fill_fragment(a1, 0.0f);
#pragma unroll
            for (int dc = 0; dc < 8; dc++){
                FragA qh, ql;
                wm::load_matrix_sync(qh, g_Qh + qofs + dc*8, DKK);
                wm::load_matrix_sync(ql, g_Ql + qofs + dc*8, DKK);
                FragBc bh0, bl0, bh1, bl1;
                wm::load_matrix_sync(bh0, Khp + t0*DKK + dc*8, DKK);
                wm::load_matrix_sync(bl0, Klp + t0*DKK + dc*8, DKK);
                wm::load_matrix_sync(bh1, Khp + t1*DKK + dc*8, DKK);
                wm::load_matrix_sync(bl1, Klp + t1*DKK + dc*8, DKK);
                wm::mma_sync(a0, qh, bh0, a0);
                wm::mma_sync(a1, qh, bh1, a1);
                wm::mma_sync(a0, qh, bl0, a0);
                wm::mma_sync(a1, qh, bl1, a1);
                wm::mma_sync(a0, ql, bh0, a0);
                wm::mma_sync(a1, ql, bh1, a1);
            }
            wm::store_matrix_sync(sc + t0, a0, 2056, wm::mem_row_major);
            wm::store_matrix_sync(sc + t1, a1, 2056, wm::mem_row_major);
        }
    }
    __syncthreads();

    // ---- Phase B: warp w -> softmax row w
    {
        float* row = sc + w*2056;
        float m = -3.4e38f;
        for (int c = lane; c < SS; c += 32) m = fmaxf(m, row[c]);
#pragma unroll
        for (int o = 16; o > 0; o >>= 1) m = fmaxf(m, __shfl_xor_sync(0xffffffffu, m, o));
        float sum = 0.f;
        for (int c = lane; c < SS; c += 32){
            float e = __expf(row[c] - m);
            row[c] = e;
            sum += e;
        }
#pragma unroll
        for (int o = 16; o > 0; o >>= 1) sum += __shfl_xor_sync(0xffffffffu, sum, o);
        float inv = 1.0f / sum;
        if (lane == 0) sinv[w] = inv;
        float* ow = d_out + (size_t)ZSIZE + (size_t)n*SS*SS + (size_t)(q0 + w)*SS;
        for (int c = lane; c < SS; c += 32){
            float e = row[c];
            ow[c]  = e * inv;          // exact attn_w
            row[c] = f2tf32(e);        // exact-tf32 P for PV
        }
    }
    __syncthreads();

    // ---- Phase C: warp w -> (key quarter qt = w>>2, d-tile nt = w&3)
    {
        const int qt = w >> 2;
        const int nt = w & 3;
        const int kbase = qt * 512;
        FragC c0, c1;
        wm::fill_fragment(c0, 0.0f);
        wm::fill_fragment(c1, 0.0f);
        for (int ks = 0; ks < 32; ks++){
            const int k0 = kbase + ks*16;
            FragA p0, p1;
            wm::load_matrix_sync(p0, sc + k0,     2056);
            wm::load_matrix_sync(p1, sc + k0 + 8, 2056);
            FragBr vh0, vl0, vh1, vl1;
            wm::load_matrix_sync(vh0, Vhp + (k0    )*DKK + nt*16, DKK);
            wm::load_matrix_sync(vl0, Vlp + (k0    )*DKK + nt*16, DKK);
            wm::load_matrix_sync(vh1, Vhp + (k0 + 8)*DKK + nt*16, DKK);
            wm::load_matrix_sync(vl1, Vlp + (k0 + 8)*DKK + nt*16, DKK);
            wm::mma_sync(c0, p0, vh0, c0);
            wm::mma_sync(c1, p1, vh1, c1);
            wm::mma_sync(c0, p0, vl0, c0);
            wm::mma_sync(c1, p1, vl1, c1);
        }
#pragma unroll
        for (int i = 0; i < c0.num_elements; i++) c0.x[i] += c1.x[i];
        wm::store_matrix_sync(pvb + w*256, c0, 16, wm::mem_row_major);
    }
    __syncthreads();

    // ---- reduce 4 key-quarters, scale, split, store flat [q][n][d]
    for (int idx = t; idx < 1024; idx += 512){
        int q  = idx >> 6;
        int d  = idx & 63;
        int nt = d >> 4;
        int dl = d & 15;
        float v = pvb[(0*4+nt)*256 + q*16 + dl]
                + pvb[(1*4+nt)*256 + q*16 + dl]
                + pvb[(2*4+nt)*256 + q*16 + dl]
                + pvb[(3*4+nt)*256 + q*16 + dl];
        v *= sinv[q];
        float h = f2tf32(v);
        size_t o = (size_t)(q0 + q)*(NH*DKK) + n*DKK + d;
        g_AOh[o] = h;
        g_AOl[o] = v - h;
    }
}

// ---------------------------------------------------------------------------
// Kernel 3: out-projection + transpose store.  Pre-split AO and Wo.
// grid (64 row-tiles, 4 col-tiles), 256 threads.
// ---------------------------------------------------------------------------
__global__ void __launch_bounds__(256) oproj_kernel(
        const float* __restrict__ bo, float* __restrict__ d_out)
{
    __shared__ __align__(128) float sbuf[64*132];   // C col-major [e][r]

    const int r0 = blockIdx.x * 128;
    const int e0 = blockIdx.y * 64;
    const int t  = threadIdx.x;
    const int w  = t >> 5;
    const int wmw = w >> 1;     // 0..3
    const int wnw = w & 1;      // 0..1

    FragC acc[2][2];
#pragma unroll
    for (int a=0;a<2;a++)
#pragma unroll
        for (int b2=0;b2<2;b2++) wm::fill_fragment(acc[a][b2], 0.0f);

    for (int ks = 0; ks < 64; ks++){
        FragA ahi[2], alo[2];
#pragma unroll
        for (int mt = 0; mt < 2; mt++){
            size_t aofs = (size_t)(r0 + wmw*32 + mt*16)*DMM + ks*8;
            wm::load_matrix_sync(ahi[mt], g_AOh + aofs, DMM);
            wm::load_matrix_sync(alo[mt], g_AOl + aofs, DMM);
        }
#pragma unroll
        for (int nt = 0; nt < 2; nt++){
            FragBc bhi, blo;
            const int wofs = (e0 + wnw*32 + nt*16)*DMM + ks*8;
            wm::load_matrix_sync(bhi, g_Woh + wofs, DMM);
            wm::load_matrix_sync(blo, g_Wol + wofs, DMM);
#pragma unroll
            for (int mt = 0; mt < 2; mt++){
                wm::mma_sync(acc[mt][nt], ahi[mt], bhi, acc[mt][nt]);
                wm::mma_sync(acc[mt][nt], ahi[mt], blo, acc[mt][nt]);
                wm::mma_sync(acc[mt][nt], alo[mt], bhi, acc[mt][nt]);
            }
        }
    }

#pragma unroll
    for (int mt = 0; mt < 2; mt++)
#pragma unroll
        for (int nt = 0; nt < 2; nt++)
            wm::store_matrix_sync(sbuf + (wnw*32 + nt*16)*132 + wmw*32 + mt*16,
                                  acc[mt][nt], 132, wm::mem_col_major);
    __syncthreads();

    const int b  = r0 >> 11;
    const int s0 = r0 & 2047;
    for (int it = 0; it < 32; it++){
        int el = it*2 + (t >> 7);
        int sl = t & 127;
        float v = sbuf[el*132 + sl] + bo[e0 + el];
        d_out[(size_t)b*(DIN_*SS) + (size_t)(e0 + el)*SS + s0 + sl] = v;
    }
}

// ---------------------------------------------------------------------------
extern "C" void kernel_launch(void* const* d_in, const int* in_sizes, int n_in,
                              void* d_out, int out_size)
{
    const float* x  = (const float*)d_in[0];
    const float* Wq = (const float*)d_in[1];
    const float* bq = (const float*)d_in[2];
    const float* Wk = (const float*)d_in[3];
    const float* bk = (const float*)d_in[4];
    const float* Wv = (const float*)d_in[5];
    const float* bv = (const float*)d_in[6];
    const float* Wo = (const float*)d_in[7];
    const float* bo = (const float*)d_in[8];
    float* out = (float*)d_out;

    float *wqh, *wql, *wkh, *wkl, *wvh, *wvl, *woh, *wol;
    cudaGetSymbolAddress((void**)&wqh, g_Wqh); cudaGetSymbolAddress((void**)&wql, g_Wql);
    cudaGetSymbolAddress((void**)&wkh, g_Wkh); cudaGetSymbolAddress((void**)&wkl, g_Wkl);
    cudaGetSymbolAddress((void**)&wvh, g_Wvh); cudaGetSymbolAddress((void**)&wvl, g_Wvl);
    cudaGetSymbolAddress((void**)&woh, g_Woh); cudaGetSymbolAddress((void**)&wol, g_Wol);

    const int nw = DMM * DIN_;   // 131072
    split_w_kernel<<<nw/256, 256>>>(Wq, wqh, wql, nw);
    split_w_kernel<<<nw/256, 256>>>(Wk, wkh, wkl, nw);
    split_w_kernel<<<nw/256, 256>>>(Wv, wvh, wvl, nw);
    split_w_kernel<<<nw/256, 256>>>(Wo, woh, wol, nw);

    const int attn_smem = (16*2056 + 16*256 + 16) * 4;   // 148,032 B
    cudaFuncSetAttribute(attn_kernel, cudaFuncAttributeMaxDynamicSharedMemorySize, attn_smem);

    qkv_kernel<<<dim3(128, 4, 3), 256>>>(x, bq, bk, bv);
    attn_kernel<<<dim3(128, 32), 512, attn_smem>>>(out);
    oproj_kernel<<<dim3(64, 4), 256>>>(bo, out);
}

// round 11
// speedup vs baseline: 1.9874x; 1.7527x over previous
#include <cuda_runtime.h>
#include <cuda_bf16.h>
#include <mma.h>
#include <cstdint>

namespace wm = nvcuda::wmma;

#define BB   4
#define DIN_ 256
#define SS   2048
#define DMM  512
#define HH   8
#define DKK  64
#define NH   32                      // B*H
#define ZSIZE (BB*DIN_*SS)           // 2097152

typedef __nv_bfloat16 bf16;

// ---- device-global scratch (allocation-free rule) -------------------------
__device__ bf16  g_Qbh[NH*SS*DKK], g_Qbl[NH*SS*DKK];
__device__ bf16  g_Kbh[NH*SS*DKK], g_Kbl[NH*SS*DKK];
__device__ float g_V  [NH*SS*DKK];
__device__ float g_AOh[SS*NH*DKK], g_AOl[SS*NH*DKK];   // flat [S][B*H][dk]
__device__ bf16  g_Wqbh[DMM*DIN_], g_Wqbl[DMM*DIN_];
__device__ bf16  g_Wkbh[DMM*DIN_], g_Wkbl[DMM*DIN_];
__device__ bf16  g_Wvbh[DMM*DIN_], g_Wvbl[DMM*DIN_];
__device__ float g_Woh[DIN_*DMM],  g_Wol[DIN_*DMM];

__device__ __forceinline__ float f2tf32(float x){
    float r; asm("cvt.rna.tf32.f32 %0, %1;" : "=f"(r) : "f"(x)); return r;
}

// bf16 fragments (m16n16k16)
using BFragA  = wm::fragment<wm::matrix_a,    16,16,16, bf16, wm::row_major>;
using BFragBc = wm::fragment<wm::matrix_b,    16,16,16, bf16, wm::col_major>;
using BFragC  = wm::fragment<wm::accumulator, 16,16,16, float>;
// tf32 fragments (m16n16k8)
using TFragA  = wm::fragment<wm::matrix_a,    16,16,8, wm::precision::tf32, wm::row_major>;
using TFragBc = wm::fragment<wm::matrix_b,    16,16,8, wm::precision::tf32, wm::col_major>;
using TFragBr = wm::fragment<wm::matrix_b,    16,16,8, wm::precision::tf32, wm::row_major>;
using TFragC  = wm::fragment<wm::accumulator, 16,16,8, float>;

// ---------------------------------------------------------------------------
// Kernel 0a: split fp32 weights into bf16 hi/lo.
// ---------------------------------------------------------------------------
__global__ void split_w_bf16(const float* __restrict__ s,
                             bf16* __restrict__ h, bf16* __restrict__ l, int n)
{
    int i = blockIdx.x * 256 + threadIdx.x;
    if (i < n){
        float v = s[i];
        bf16 hh = __float2bfloat16(v);
        h[i] = hh;
        l[i] = __float2bfloat16(v - __bfloat162float(hh));
    }
}
// Kernel 0b: split fp32 weights into tf32 hi/lo (for Wo).
__global__ void split_w_f32(const float* __restrict__ s,
                            float* __restrict__ h, float* __restrict__ l, int n)
{
    int i = blockIdx.x * 256 + threadIdx.x;
    if (i < n){ float v = s[i]; float hh = f2tf32(v); h[i] = hh; l[i] = v - hh; }
}

// ---------------------------------------------------------------------------
// Kernel 1: QKV projections, bf16x2 (3-product) emulated fp32.
//   rows r = s*4 + b (xt); output per-head: Q,K -> bf16 hi/lo, V -> fp32.
// grid (128 row-tiles, 4 col-tiles, 3={Q,K,V}), 256 threads.
// ---------------------------------------------------------------------------
__global__ void __launch_bounds__(256) qkv_kernel(
        const float* __restrict__ x,
        const float* __restrict__ bq, const float* __restrict__ bk,
        const float* __restrict__ bv)
{
    __shared__ __align__(16) char sraw[64*132*4];      // union: A hi/lo bf16 | C fp32
    bf16*  shi  = (bf16*)sraw;                         // [64][40]
    bf16*  slo  = shi + 64*40;
    float* sC   = (float*)sraw;                        // [64][132]

    const int which = blockIdx.z;
    const bf16* Wh    = (which==0) ? g_Wqbh : (which==1 ? g_Wkbh : g_Wvbh);
    const bf16* Wl    = (which==0) ? g_Wqbl : (which==1 ? g_Wkbl : g_Wvbl);
    const float* bias = (which==0) ? bq    : (which==1 ? bk    : bv);

    const int r0 = blockIdx.x * 64;       // rows r = s*4+b
    const int m0 = blockIdx.y * 128;
    const int s0 = r0 >> 2;
    const int t  = threadIdx.x;
    const int w  = t >> 5;
    const int wmw = w >> 2;               // 0..1
    const int wnw = w & 3;                // 0..3

    BFragC acc[2][2];
#pragma unroll
    for (int a=0;a<2;a++)
#pragma unroll
        for (int b2=0;b2<2;b2++) wm::fill_fragment(acc[a][b2], 0.0f);

    for (int kc = 0; kc < DIN_; kc += 32){
#pragma unroll
        for (int j = 0; j < 8; j++){
            int idx = j*256 + t;
            int sl  = idx & 15;
            int p   = idx >> 4;
            int bb  = p & 3;
            int il  = p >> 2;
            float v = x[bb*(DIN_*SS) + (kc+il)*SS + (s0+sl)];
            bf16 h  = __float2bfloat16(v);
            int pos = (sl*4 + bb)*40 + il;
            shi[pos] = h;
            slo[pos] = __float2bfloat16(v - __bfloat162float(h));
        }
        __syncthreads();

#pragma unroll
        for (int ks = 0; ks < 2; ks++){
            BFragA ahi[2], alo[2];
#pragma unroll
            for (int mt = 0; mt < 2; mt++){
                wm::load_matrix_sync(ahi[mt], shi + (wmw*32 + mt*16)*40 + ks*16, 40);
                wm::load_matrix_sync(alo[mt], slo + (wmw*32 + mt*16)*40 + ks*16, 40);
            }
#pragma unroll
            for (int nt = 0; nt < 2; nt++){
                BFragBc bhi, blo;
                const int wofs = (m0 + wnw*32 + nt*16)*DIN_ + kc + ks*16;
                wm::load_matrix_sync(bhi, Wh + wofs, DIN_);
                wm::load_matrix_sync(blo, Wl + wofs, DIN_);
#pragma unroll
                for (int mt = 0; mt < 2; mt++){
                    wm::mma_sync(acc[mt][nt], ahi[mt], bhi, acc[mt][nt]);
                    wm::mma_sync(acc[mt][nt], ahi[mt], blo, acc[mt][nt]);
                    wm::mma_sync(acc[mt][nt], alo[mt], bhi, acc[mt][nt]);
                }
            }
        }
        __syncthreads();
    }

#pragma unroll
    for (int mt = 0; mt < 2; mt++)
#pragma unroll
        for (int nt = 0; nt < 2; nt++)
            wm::store_matrix_sync(sC + (wmw*32 + mt*16)*132 + wnw*32 + nt*16,
                                  acc[mt][nt], 132, wm::mem_row_major);
    __syncthreads();

#pragma unroll
    for (int it = 0; it < 32; it++){
        int rl = it*2 + (t >> 7);
        int ml = t & 127;
        int m  = m0 + ml;
        float v = sC[rl*132 + ml] + bias[m];
        int s  = s0 + (rl >> 2);
        int bb = rl & 3;
        int h  = m >> 6;
        int d  = m & 63;
        size_t o = (size_t)((bb*HH + h)*SS + s)*DKK + d;
        if (which == 2){
            g_V[o] = v;
        } else {
            bf16 hh = __float2bfloat16(v);
            bf16 ll = __float2bfloat16(v - __bfloat162float(hh));
            if (which == 0){ g_Qbh[o] = hh; g_Qbl[o] = ll; }
            else           { g_Kbh[o] = hh; g_Kbl[o] = ll; }
        }
    }
}

// ---------------------------------------------------------------------------
// Kernel 2: attention.  CTA = (head n, 16 q-rows), 512 threads (16 warps).
//   Phase A: QK^T bf16x2 (3 MMAs/chunk), K staged cooperatively in smem.
//   Phase B: softmax fp32; exact attn_w write (float4); P -> exact tf32.
//   Phase C: PV tf32 (P exact-tf32 x V hi/lo), V fp32 staged in smem.
// grid (128 q-tiles, 32 heads), 221.8KB dyn smem.
// ---------------------------------------------------------------------------
#define SC_LD 2056
#define ST_LD 72
__global__ void __launch_bounds__(512) attn_kernel(float* __restrict__ d_out)
{
    extern __shared__ __align__(16) char smraw[];
    float* sc  = (float*)smraw;                               // [16][2056] fp32
    bf16*  ksh = (bf16*)(smraw + 16*SC_LD*4);                 // [256][72] bf16
    bf16*  ksl = ksh + 256*ST_LD;                             // [256][72] bf16
    float* vst = (float*)ksh;                                 // [256][72] fp32 (aliases K stage)
    float* pvb = (float*)(smraw + 16*SC_LD*4 + 2*256*ST_LD*2);// [16][256]
    float* sinv = pvb + 16*256;                               // [16]

    const int n    = blockIdx.y;
    const int q0   = blockIdx.x * 16;
    const int t    = threadIdx.x;
    const int w    = t >> 5;                // 0..15
    const int lane = t & 31;

    const bf16* Qh = g_Qbh + (size_t)(n*SS + q0)*DKK;
    const bf16* Ql = g_Qbl + (size_t)(n*SS + q0)*DKK;
    const bf16* Kh = g_Kbh + (size_t)n*SS*DKK;
    const bf16* Kl = g_Kbl + (size_t)n*SS*DKK;
    const float* Vg = g_V  + (size_t)n*SS*DKK;

    // hoisted Q fragments (4 k16 chunks, hi/lo)
    BFragA qh[4], ql[4];
#pragma unroll
    for (int dc = 0; dc < 4; dc++){
        wm::load_matrix_sync(qh[dc], Qh + dc*16, DKK);
        wm::load_matrix_sync(ql[dc], Ql + dc*16, DKK);
    }

    // ---- Phase A: 8 key-blocks of 256; stage K hi/lo, warp w -> 16 keys
    for (int kb = 0; kb < SS; kb += 256){
        const bf16* srcH = Kh + (size_t)kb*DKK;
        const bf16* srcL = Kl + (size_t)kb*DKK;
#pragma unroll
        for (int i = 0; i < 4; i++){
            int idx = i*512 + t;
            int r = idx >> 3, j = idx & 7;
            *(uint4*)(ksh + r*ST_LD + j*8) = *(const uint4*)(srcH + r*DKK + j*8);
            *(uint4*)(ksl + r*ST_LD + j*8) = *(const uint4*)(srcL + r*DKK + j*8);
        }
        __syncthreads();

        BFragC acc; wm::fill_fragment(acc, 0.0f);
        const bf16* bh_base = ksh + (w*16)*ST_LD;
        const bf16* bl_base = ksl + (w*16)*ST_LD;
#pragma unroll
        for (int dc = 0; dc < 4; dc++){
            BFragBc bh, bl;
            wm::load_matrix_sync(bh, bh_base + dc*16, ST_LD);
            wm::load_matrix_sync(bl, bl_base + dc*16, ST_LD);
            wm::mma_sync(acc, qh[dc], bh, acc);
            wm::mma_sync(acc, qh[dc], bl, acc);
            wm::mma_sync(acc, ql[dc], bh, acc);
        }
        wm::store_matrix_sync(sc + kb + w*16, acc, SC_LD, wm::mem_row_major);
        __syncthreads();
    }

    // ---- Phase B: warp w -> softmax of row w (float4 passes)
    {
        float* row = sc + w*SC_LD;
        float4* row4 = (float4*)row;
        float m = -3.4e38f;
        for (int c = lane; c < 512; c += 32){
            float4 v = row4[c];
            m = fmaxf(m, fmaxf(fmaxf(v.x, v.y), fmaxf(v.z, v.w)));
        }
#pragma unroll
        for (int o = 16; o > 0; o >>= 1) m = fmaxf(m, __shfl_xor_sync(0xffffffffu, m, o));
        float sum = 0.f;
        for (int c = lane; c < 512; c += 32){
            float4 v = row4[c];
            v.x = __expf(v.x - m); v.y = __expf(v.y - m);
            v.z = __expf(v.z - m); v.w = __expf(v.w - m);
            row4[c] = v;
            sum += (v.x + v.y) + (v.z + v.w);
        }
#pragma unroll
        for (int o = 16; o > 0; o >>= 1) sum += __shfl_xor_sync(0xffffffffu, sum, o);
        float inv = 1.0f / sum;
        if (lane == 0) sinv[w] = inv;
        float4* ow4 = (float4*)(d_out + (size_t)ZSIZE + (size_t)n*SS*SS + (size_t)(q0 + w)*SS);
        for (int c = lane; c < 512; c += 32){
            float4 e = row4[c];
            float4 o4 = make_float4(e.x*inv, e.y*inv, e.z*inv, e.w*inv);
            ow4[c] = o4;                                  // exact attn_w
            e.x = f2tf32(e.x); e.y = f2tf32(e.y);
            e.z = f2tf32(e.z); e.w = f2tf32(e.w);
            row4[c] = e;                                  // exact-tf32 P
        }
    }

    // ---- Phase C: PV.  stage V fp32 per 256-key block.
    //      warp w: d-tile nt = w&3, key quarter qt = w>>2 (64 keys/block).
    const int nt = w & 3;
    const int qt = w >> 2;
    TFragC acc; wm::fill_fragment(acc, 0.0f);
    for (int kb = 0; kb < SS; kb += 256){
        const float* src = Vg + (size_t)kb*DKK;
#pragma unroll
        for (int i = 0; i < 8; i++){
            int idx = i*512 + t;
            int r = idx >> 4, j = idx & 15;
            *(uint4*)(vst + r*ST_LD + j*4) = *(const uint4*)(src + r*DKK + j*4);
        }
        __syncthreads();

#pragma unroll
        for (int ks = 0; ks < 8; ks++){
            const int kl = qt*64 + ks*8;         // key local to block
            TFragA p;
            wm::load_matrix_sync(p, sc + kb + kl, SC_LD);
            TFragBr vraw, vh, vl;
            wm::load_matrix_sync(vraw, vst + kl*ST_LD + nt*16, ST_LD);
#pragma unroll
            for (int i = 0; i < vraw.num_elements; i++){
                float h = f2tf32(vraw.x[i]);
                vh.x[i] = h;
                vl.x[i] = f2tf32(vraw.x[i] - h);
            }
            wm::mma_sync(acc, p, vh, acc);
            wm::mma_sync(acc, p, vl, acc);
        }
        __syncthreads();
    }
    wm::store_matrix_sync(pvb + w*256, acc, 16, wm::mem_row_major);
    __syncthreads();

    // ---- reduce 4 key-quarters, scale, split to tf32 hi/lo, store [s][n][d]
#pragma unroll
    for (int u = 0; u < 2; u++){
        int idx = u*512 + t;
        int q  = idx >> 6;
        int d  = idx & 63;
        int ntd = d >> 4;
        int dl = d & 15;
        float v = pvb[(0*4+ntd)*256 + q*16 + dl]
                + pvb[(1*4+ntd)*256 + q*16 + dl]
                + pvb[(2*4+ntd)*256 + q*16 + dl]
                + pvb[(3*4+ntd)*256 + q*16 + dl];
        v *= sinv[q];
        float h = f2tf32(v);
        size_t o = (size_t)(q0 + q)*(NH*DKK) + n*DKK + d;
        g_AOh[o] = h;
        g_AOl[o] = v - h;
    }
}

// ---------------------------------------------------------------------------
// Kernel 3: out-projection + transpose store (tf32 split-3, pre-split).
// grid (64 row-tiles, 4 col-tiles), 256 threads.
// ---------------------------------------------------------------------------
__global__ void __launch_bounds__(256) oproj_kernel(
        const float* __restrict__ bo, float* __restrict__ d_out)
{
    __shared__ __align__(128) float sbuf[64*132];   // C col-major [e][r]

    const int r0 = blockIdx.x * 128;
    const int e0 = blockIdx.y * 64;
    const int t  = threadIdx.x;
    const int w  = t >> 5;
    const int wmw = w >> 1;     // 0..3
    const int wnw = w & 1;      // 0..1

    TFragC acc[2][2];
#pragma unroll
    for (int a=0;a<2;a++)
#pragma unroll
        for (int b2=0;b2<2;b2++) wm::fill_fragment(acc[a][b2], 0.0f);

    for (int ks = 0; ks < 64; ks++){
        TFragA ahi[2], alo[2];
#pragma unroll
        for (int mt = 0; mt < 2; mt++){
            size_t aofs = (size_t)(r0 + wmw*32 + mt*16)*DMM + ks*8;
            wm::load_matrix_sync(ahi[mt], g_AOh + aofs, DMM);
            wm::load_matrix_sync(alo[mt], g_AOl + aofs, DMM);
        }
#pragma unroll
        for (int nt = 0; nt < 2; nt++){
            TFragBc bhi, blo;
            const int wofs = (e0 + wnw*32 + nt*16)*DMM + ks*8;
            wm::load_matrix_sync(bhi, g_Woh + wofs, DMM);
            wm::load_matrix_sync(blo, g_Wol + wofs, DMM);
#pragma unroll
            for (int mt = 0; mt < 2; mt++){
                wm::mma_sync(acc[mt][nt], ahi[mt], bhi, acc[mt][nt]);
                wm::mma_sync(acc[mt][nt], ahi[mt], blo, acc[mt][nt]);
                wm::mma_sync(acc[mt][nt], alo[mt], bhi, acc[mt][nt]);
            }
        }
    }

#pragma unroll
    for (int mt = 0; mt < 2; mt++)
#pragma unroll
        for (int nt = 0; nt < 2; nt++)
            wm::store_matrix_sync(sbuf + (wnw*32 + nt*16)*132 + wmw*32 + mt*16,
                                  acc[mt][nt], 132, wm::mem_col_major);
    __syncthreads();

    const int b  = r0 >> 11;
    const int s0 = r0 & 2047;
#pragma unroll
    for (int it = 0; it < 32; it++){
        int el = it*2 + (t >> 7);
        int sl = t & 127;
        float v = sbuf[el*132 + sl] + bo[e0 + el];
        d_out[(size_t)b*(DIN_*SS) + (size_t)(e0 + el)*SS + s0 + sl] = v;
    }
}

// ---------------------------------------------------------------------------
extern "C" void kernel_launch(void* const* d_in, const int* in_sizes, int n_in,
                              void* d_out, int out_size)
{
    const float* x  = (const float*)d_in[0];
    const float* Wq = (const float*)d_in[1];
    const float* bq = (const float*)d_in[2];
    const float* Wk = (const float*)d_in[3];
    const float* bk = (const float*)d_in[4];
    const float* Wv = (const float*)d_in[5];
    const float* bv = (const float*)d_in[6];
    const float* Wo = (const float*)d_in[7];
    const float* bo = (const float*)d_in[8];
    float* out = (float*)d_out;

    bf16 *wqh, *wql, *wkh, *wkl, *wvh, *wvl;
    float *woh, *wol;
    cudaGetSymbolAddress((void**)&wqh, g_Wqbh); cudaGetSymbolAddress((void**)&wql, g_Wqbl);
    cudaGetSymbolAddress((void**)&wkh, g_Wkbh); cudaGetSymbolAddress((void**)&wkl, g_Wkbl);
    cudaGetSymbolAddress((void**)&wvh, g_Wvbh); cudaGetSymbolAddress((void**)&wvl, g_Wvbl);
    cudaGetSymbolAddress((void**)&woh, g_Woh);  cudaGetSymbolAddress((void**)&wol, g_Wol);

    const int nw = DMM * DIN_;   // 131072
    split_w_bf16<<<nw/256, 256>>>(Wq, wqh, wql, nw);
    split_w_bf16<<<nw/256, 256>>>(Wk, wkh, wkl, nw);
    split_w_bf16<<<nw/256, 256>>>(Wv, wvh, wvl, nw);
    split_w_f32 <<<nw/256, 256>>>(Wo, woh, wol, nw);

    // smem: sc 131584 + Kstage(2*36864=73728) + pvb 16384 + sinv 64 = 221760
    const int attn_smem = 16*SC_LD*4 + 2*256*ST_LD*2 + 16*256*4 + 64;
    cudaFuncSetAttribute(attn_kernel, cudaFuncAttributeMaxDynamicSharedMemorySize, attn_smem);

    qkv_kernel<<<dim3(128, 4, 3), 256>>>(x, bq, bk, bv);
    attn_kernel<<<dim3(128, 32), 512, attn_smem>>>(out);
    oproj_kernel<<<dim3(64, 4), 256>>>(bo, out);
}

// round 13
// speedup vs baseline: 2.4824x; 1.2491x over previous
#include <cuda_runtime.h>
#include <cuda_bf16.h>
#include <mma.h>
#include <cstdint>

namespace wm = nvcuda::wmma;

#define BB   4
#define DIN_ 256
#define SS   2048
#define DMM  512
#define HH   8
#define DKK  64
#define NH   32                      // B*H
#define ZSIZE (BB*DIN_*SS)           // 2097152

typedef __nv_bfloat16 bf16;

// ---- device-global scratch (allocation-free rule) -------------------------
__device__ bf16  g_Qbh[NH*SS*DKK], g_Qbl[NH*SS*DKK];
__device__ bf16  g_Kbh[NH*SS*DKK], g_Kbl[NH*SS*DKK];
__device__ float g_V  [NH*SS*DKK];
__device__ float g_AOh[SS*NH*DKK], g_AOl[SS*NH*DKK];   // flat [S][B*H][dk]
__device__ bf16  g_Wqbh[DMM*DIN_], g_Wqbl[DMM*DIN_];
__device__ bf16  g_Wkbh[DMM*DIN_], g_Wkbl[DMM*DIN_];
__device__ bf16  g_Wvbh[DMM*DIN_], g_Wvbl[DMM*DIN_];
__device__ float g_Woh[DIN_*DMM],  g_Wol[DIN_*DMM];

__device__ __forceinline__ float f2tf32(float x){
    float r; asm("cvt.rna.tf32.f32 %0, %1;" : "=f"(r) : "f"(x)); return r;
}

// bf16 fragments (m16n16k16)
using BFragA  = wm::fragment<wm::matrix_a,    16,16,16, bf16, wm::row_major>;
using BFragBc = wm::fragment<wm::matrix_b,    16,16,16, bf16, wm::col_major>;
using BFragC  = wm::fragment<wm::accumulator, 16,16,16, float>;
// tf32 fragments (m16n16k8)
using TFragA  = wm::fragment<wm::matrix_a,    16,16,8, wm::precision::tf32, wm::row_major>;
using TFragBc = wm::fragment<wm::matrix_b,    16,16,8, wm::precision::tf32, wm::col_major>;
using TFragBr = wm::fragment<wm::matrix_b,    16,16,8, wm::precision::tf32, wm::row_major>;
using TFragC  = wm::fragment<wm::accumulator, 16,16,8, float>;

// ---------------------------------------------------------------------------
// Kernel 0a: split fp32 weights into bf16 hi/lo.
// ---------------------------------------------------------------------------
__global__ void split_w_bf16(const float* __restrict__ s,
                             bf16* __restrict__ h, bf16* __restrict__ l, int n)
{
    int i = blockIdx.x * 256 + threadIdx.x;
    if (i < n){
        float v = s[i];
        bf16 hh = __float2bfloat16(v);
        h[i] = hh;
        l[i] = __float2bfloat16(v - __bfloat162float(hh));
    }
}
// Kernel 0b: split fp32 weights into tf32 hi/lo (for Wo).
__global__ void split_w_f32(const float* __restrict__ s,
                            float* __restrict__ h, float* __restrict__ l, int n)
{
    int i = blockIdx.x * 256 + threadIdx.x;
    if (i < n){ float v = s[i]; float hh = f2tf32(v); h[i] = hh; l[i] = v - hh; }
}

// ---------------------------------------------------------------------------
// Kernel 1: QKV projections, bf16x2 (3-product) emulated fp32.  (unchanged)
// ---------------------------------------------------------------------------
__global__ void __launch_bounds__(256) qkv_kernel(
        const float* __restrict__ x,
        const float* __restrict__ bq, const float* __restrict__ bk,
        const float* __restrict__ bv)
{
    __shared__ __align__(16) char sraw[64*132*4];      // union: A hi/lo bf16 | C fp32
    bf16*  shi  = (bf16*)sraw;                         // [64][40]
    bf16*  slo  = shi + 64*40;
    float* sC   = (float*)sraw;                        // [64][132]

    const int which = blockIdx.z;
    const bf16* Wh    = (which==0) ? g_Wqbh : (which==1 ? g_Wkbh : g_Wvbh);
    const bf16* Wl    = (which==0) ? g_Wqbl : (which==1 ? g_Wkbl : g_Wvbl);
    const float* bias = (which==0) ? bq    : (which==1 ? bk    : bv);

    const int r0 = blockIdx.x * 64;       // rows r = s*4+b
    const int m0 = blockIdx.y * 128;
    const int s0 = r0 >> 2;
    const int t  = threadIdx.x;
    const int w  = t >> 5;
    const int wr = w >> 2;                // 0..1
    const int wc = w & 3;                 // 0..3

    BFragC acc[2][2];
#pragma unroll
    for (int a=0;a<2;a++)
#pragma unroll
        for (int b2=0;b2<2;b2++) wm::fill_fragment(acc[a][b2], 0.0f);

    for (int kc = 0; kc < DIN_; kc += 32){
#pragma unroll
        for (int j = 0; j < 8; j++){
            int idx = j*256 + t;
            int sl  = idx & 15;
            int p   = idx >> 4;
            int bb  = p & 3;
            int il  = p >> 2;
            float v = x[bb*(DIN_*SS) + (kc+il)*SS + (s0+sl)];
            bf16 h  = __float2bfloat16(v);
            int pos = (sl*4 + bb)*40 + il;
            shi[pos] = h;
            slo[pos] = __float2bfloat16(v - __bfloat162float(h));
        }
        __syncthreads();

#pragma unroll
        for (int ks = 0; ks < 2; ks++){
            BFragA ahi[2], alo[2];
#pragma unroll
            for (int mt = 0; mt < 2; mt++){
                wm::load_matrix_sync(ahi[mt], shi + (wr*32 + mt*16)*40 + ks*16, 40);
                wm::load_matrix_sync(alo[mt], slo + (wr*32 + mt*16)*40 + ks*16, 40);
            }
#pragma unroll
            for (int nt = 0; nt < 2; nt++){
                BFragBc bhi, blo;
                const int wofs = (m0 + wc*32 + nt*16)*DIN_ + kc + ks*16;
                wm::load_matrix_sync(bhi, Wh + wofs, DIN_);
                wm::load_matrix_sync(blo, Wl + wofs, DIN_);
#pragma unroll
                for (int mt = 0; mt < 2; mt++){
                    wm::mma_sync(acc[mt][nt], ahi[mt], bhi, acc[mt][nt]);
                    wm::mma_sync(acc[mt][nt], ahi[mt], blo, acc[mt][nt]);
                    wm::mma_sync(acc[mt][nt], alo[mt], bhi, acc[mt][nt]);
                }
            }
        }
        __syncthreads();
    }

#pragma unroll
    for (int mt = 0; mt < 2; mt++)
#pragma unroll
        for (int nt = 0; nt < 2; nt++)
            wm::store_matrix_sync(sC + (wr*32 + mt*16)*132 + wc*32 + nt*16,
                                  acc[mt][nt], 132, wm::mem_row_major);
    __syncthreads();

#pragma unroll
    for (int it = 0; it < 32; it++){
        int rl = it*2 + (t >> 7);
        int ml = t & 127;
        int m  = m0 + ml;
        float v = sC[rl*132 + ml] + bias[m];
        int s  = s0 + (rl >> 2);
        int bb = rl & 3;
        int h  = m >> 6;
        int d  = m & 63;
        size_t o = (size_t)((bb*HH + h)*SS + s)*DKK + d;
        if (which == 2){
            g_V[o] = v;
        } else {
            bf16 hh = __float2bfloat16(v);
            bf16 ll = __float2bfloat16(v - __bfloat162float(hh));
            if (which == 0){ g_Qbh[o] = hh; g_Qbl[o] = ll; }
            else           { g_Kbh[o] = hh; g_Kbl[o] = ll; }
        }
    }
}

// ---------------------------------------------------------------------------
// Kernel 2a: scores = Q K^T (bf16x2, 3 MMA/k16).  Tiled GEMM, raw scores
//   written straight into the attn_w region of d_out (scratch before softmax).
// CTA tile 128q x 128k, 8 warps, warp = (wr=w>>2: 4 m-tiles, wc=w&3: 2 n-tiles).
// grid (16 q-tiles, 16 k-tiles, 32 heads), 72KB dyn smem, 2 CTA/SM.
// ---------------------------------------------------------------------------
#define SK_LD 72
__global__ void __launch_bounds__(256, 2) score_kernel(float* __restrict__ d_out)
{
    extern __shared__ __align__(16) bf16 sks[];
    bf16* sQh = sks;                    // [128][72]
    bf16* sQl = sQh + 128*SK_LD;
    bf16* sKh = sQl + 128*SK_LD;
    bf16* sKl = sKh + 128*SK_LD;

    const int q0 = blockIdx.x * 128;
    const int k0 = blockIdx.y * 128;
    const int n  = blockIdx.z;
    const int t  = threadIdx.x;
    const int w  = t >> 5;
    const int wr = w >> 2;              // 0..1 -> 4 m-tiles each
    const int wc = w & 3;               // 0..3 -> 2 n-tiles each

    const bf16* Qhg = g_Qbh + ((size_t)n*SS + q0)*DKK;
    const bf16* Qlg = g_Qbl + ((size_t)n*SS + q0)*DKK;
    const bf16* Khg = g_Kbh + ((size_t)n*SS + k0)*DKK;
    const bf16* Klg = g_Kbl + ((size_t)n*SS + k0)*DKK;

    // stage Q and K tiles: 128 rows x 8 uint4 (64 bf16) per array = 1024 uint4
#pragma unroll
    for (int i = 0; i < 4; i++){
        int idx = i*256 + t;            // 0..1023
        int r = idx >> 3, j = idx & 7;  // r: 0..127, j: 0..7
        *(uint4*)(sQh + r*SK_LD + j*8) = *(const uint4*)(Qhg + r*DKK + j*8);
        *(uint4*)(sQl + r*SK_LD + j*8) = *(const uint4*)(Qlg + r*DKK + j*8);
        *(uint4*)(sKh + r*SK_LD + j*8) = *(const uint4*)(Khg + r*DKK + j*8);
        *(uint4*)(sKl + r*SK_LD + j*8) = *(const uint4*)(Klg + r*DKK + j*8);
    }
    __syncthreads();

    BFragC acc[4][2];
#pragma unroll
    for (int i=0;i<4;i++)
#pragma unroll
        for (int j=0;j<2;j++) wm::fill_fragment(acc[i][j], 0.0f);

#pragma unroll
    for (int ks = 0; ks < 4; ks++){
#pragma unroll
        for (int j = 0; j < 2; j++){
            const int ntr = (wc*2 + j)*16;
            BFragBc bh, bl;
            wm::load_matrix_sync(bh, sKh + ntr*SK_LD + ks*16, SK_LD);
            wm::load_matrix_sync(bl, sKl + ntr*SK_LD + ks*16, SK_LD);
#pragma unroll
            for (int i = 0; i < 4; i++){
                const int mtr = (wr*4 + i)*16;
                BFragA ah, al;
                wm::load_matrix_sync(ah, sQh + mtr*SK_LD + ks*16, SK_LD);
                wm::load_matrix_sync(al, sQl + mtr*SK_LD + ks*16, SK_LD);
                wm::mma_sync(acc[i][j], ah, bh, acc[i][j]);
                wm::mma_sync(acc[i][j], ah, bl, acc[i][j]);
                wm::mma_sync(acc[i][j], al, bh, acc[i][j]);
            }
        }
    }

    // write raw scores directly to the attn_w region (scratch)
    float* sco = d_out + (size_t)ZSIZE + (size_t)n*SS*SS;
#pragma unroll
    for (int i = 0; i < 4; i++)
#pragma unroll
        for (int j = 0; j < 2; j++)
            wm::store_matrix_sync(sco + (size_t)(q0 + (wr*4+i)*16)*SS + k0 + (wc*2+j)*16,
                                  acc[i][j], SS, wm::mem_row_major);
}

// ---------------------------------------------------------------------------
// Kernel 2b: fused softmax + PV.  CTA = (head n, 64 q-rows), 256 threads.
//   Phase 1: register-resident row softmax, in-place normalize attn_w (exact).
//   Phase 2: PV tf32: P = attn_w rounded RNA-tf32 (gmem frag loads, L1/L2-hot),
//            V fp32 staged in smem, split hi/lo in registers. 2 MMA/k8.
// grid (32 q-tiles, 32 heads), 36KB static smem.
// ---------------------------------------------------------------------------
__global__ void __launch_bounds__(256) softpv_kernel(float* __restrict__ d_out)
{
    __shared__ __align__(16) float vst[128*SK_LD];     // V stage / AO stage

    const int q0   = blockIdx.x * 64;
    const int n    = blockIdx.y;
    const int t    = threadIdx.x;
    const int w    = t >> 5;            // 0..7
    const int lane = t & 31;

    float* attw = d_out + (size_t)ZSIZE + (size_t)n*SS*SS + (size_t)q0*SS;

    // ---- Phase 1: warp w -> softmax rows w*8 .. w*8+7 (in registers)
    for (int rr = 0; rr < 8; rr++){
        float4* row4 = (float4*)(attw + (size_t)(w*8 + rr)*SS);
        float4 v[16];
        float m = -3.4e38f;
#pragma unroll
        for (int c = 0; c < 16; c++){
            v[c] = row4[lane + 32*c];
            m = fmaxf(m, fmaxf(fmaxf(v[c].x, v[c].y), fmaxf(v[c].z, v[c].w)));
        }
#pragma unroll
        for (int o = 16; o > 0; o >>= 1) m = fmaxf(m, __shfl_xor_sync(0xffffffffu, m, o));
        float sum = 0.f;
#pragma unroll
        for (int c = 0; c < 16; c++){
            v[c].x = __expf(v[c].x - m); v[c].y = __expf(v[c].y - m);
            v[c].z = __expf(v[c].z - m); v[c].w = __expf(v[c].w - m);
            sum += (v[c].x + v[c].y) + (v[c].z + v[c].w);
        }
#pragma unroll
        for (int o = 16; o > 0; o >>= 1) sum += __shfl_xor_sync(0xffffffffu, sum, o);
        float inv = 1.0f / sum;
#pragma unroll
        for (int c = 0; c < 16; c++){
            float4 e = v[c];
            row4[lane + 32*c] = make_float4(e.x*inv, e.y*inv, e.z*inv, e.w*inv);
        }
    }
    __syncthreads();   // attn_w of this CTA's 64 rows now final (gmem, block-visible)

    // ---- Phase 2: PV.  warp = (wr = w>>1: m-tile 16q, wc = w&1: 2 n-tiles)
    const int wr = w >> 1;
    const int wc = w & 1;
    const float* Vg = g_V + (size_t)n*SS*DKK;

    TFragC acc[2];
    wm::fill_fragment(acc[0], 0.0f);
    wm::fill_fragment(acc[1], 0.0f);

    for (int kb = 0; kb < 16; kb++){
        const float* src = Vg + (size_t)kb*128*DKK;
#pragma unroll
        for (int i = 0; i < 8; i++){
            int idx = i*256 + t;        // 0..2047 float4 (128 rows x 16 float4)
            int r = idx >> 4, j = idx & 15;
            *(uint4*)(vst + r*SK_LD + j*4) = *(const uint4*)(src + r*DKK + j*4);
        }
        __syncthreads();

#pragma unroll
        for (int ks = 0; ks < 16; ks++){
            TFragA p;
            wm::load_matrix_sync(p, attw + (size_t)(wr*16)*SS + kb*128 + ks*8, SS);
#pragma unroll
            for (int e = 0; e < p.num_elements; e++) p.x[e] = f2tf32(p.x[e]);
#pragma unroll
            for (int j = 0; j < 2; j++){
                const int nt = (wc*2 + j)*16;
                TFragBr vr, vh, vl;
                wm::load_matrix_sync(vr, vst + (ks*8)*SK_LD + nt, SK_LD);
#pragma unroll
                for (int e = 0; e < vr.num_elements; e++){
                    float h = f2tf32(vr.x[e]);
                    vh.x[e] = h;
                    vl.x[e] = f2tf32(vr.x[e] - h);
                }
                wm::mma_sync(acc[j], p, vh, acc[j]);
                wm::mma_sync(acc[j], p, vl, acc[j]);
            }
        }
        __syncthreads();
    }

    // epilogue: stage AO [64][68] in smem, split to tf32 hi/lo, store flat
#pragma unroll
    for (int j = 0; j < 2; j++)
        wm::store_matrix_sync(vst + (wr*16)*68 + (wc*2+j)*16, acc[j], 68, wm::mem_row_major);
    __syncthreads();

#pragma unroll
    for (int i = 0; i < 16; i++){
        int idx = i*256 + t;            // 0..4095
        int q = idx >> 6, d = idx & 63;
        float vv = vst[q*68 + d];
        float hh = f2tf32(vv);
        size_t o = (size_t)(q0 + q)*(NH*DKK) + (size_t)n*DKK + d;
        g_AOh[o] = hh;
        g_AOl[o] = vv - hh;
    }
}

// ---------------------------------------------------------------------------
// Kernel 3: out-projection + transpose store (tf32 split-3).  (unchanged)
// ---------------------------------------------------------------------------
__global__ void __launch_bounds__(256) oproj_kernel(
        const float* __restrict__ bo, float* __restrict__ d_out)
{
    __shared__ __align__(128) float sbuf[64*132];   // C col-major [e][r]

    const int r0 = blockIdx.x * 128;
    const int e0 = blockIdx.y * 64;
    const int t  = threadIdx.x;
    const int w  = t >> 5;
    const int wr = w >> 1;      // 0..3
    const int wc = w & 1;       // 0..1

    TFragC acc[2][2];
#pragma unroll
    for (int a=0;a<2;a++)
#pragma unroll
        for (int b2=0;b2<2;b2++) wm::fill_fragment(acc[a][b2], 0.0f);

    for (int ks = 0; ks < 64; ks++){
        TFragA ahi[2], alo[2];
#pragma unroll
        for (int mt = 0; mt < 2; mt++){
            size_t aofs = (size_t)(r0 + wr*32 + mt*16)*DMM + ks*8;
            wm::load_matrix_sync(ahi[mt], g_AOh + aofs, DMM);
            wm::load_matrix_sync(alo[mt], g_AOl + aofs, DMM);
        }
#pragma unroll
        for (int nt = 0; nt < 2; nt++){
            TFragBc bhi, blo;
            const int wofs = (e0 + wc*32 + nt*16)*DMM + ks*8;
            wm::load_matrix_sync(bhi, g_Woh + wofs, DMM);
            wm::load_matrix_sync(blo, g_Wol + wofs, DMM);
#pragma unroll
            for (int mt = 0; mt < 2; mt++){
                wm::mma_sync(acc[mt][nt], ahi[mt], bhi, acc[mt][nt]);
                wm::mma_sync(acc[mt][nt], ahi[mt], blo, acc[mt][nt]);
                wm::mma_sync(acc[mt][nt], alo[mt], bhi, acc[mt][nt]);
            }
        }
    }

#pragma unroll
    for (int mt = 0; mt < 2; mt++)
#pragma unroll
        for (int nt = 0; nt < 2; nt++)
            wm::store_matrix_sync(sbuf + (wc*32 + nt*16)*132 + wr*32 + mt*16,
                                  acc[mt][nt], 132, wm::mem_col_major);
    __syncthreads();

    const int b  = r0 >> 11;
    const int s0 = r0 & 2047;
#pragma unroll
    for (int it = 0; it < 32; it++){
        int el = it*2 + (t >> 7);
        int sl = t & 127;
        float v = sbuf[el*132 + sl] + bo[e0 + el];
        d_out[(size_t)b*(DIN_*SS) + (size_t)(e0 + el)*SS + s0 + sl] = v;
    }
}

// ---------------------------------------------------------------------------
extern "C" void kernel_launch(void* const* d_in, const int* in_sizes, int n_in,
                              void* d_out, int out_size)
{
    const float* x  = (const float*)d_in[0];
    const float* Wq = (const float*)d_in[1];
    const float* bq = (const float*)d_in[2];
    const float* Wk = (const float*)d_in[3];
    const float* bk = (const float*)d_in[4];
    const float* Wv = (const float*)d_in[5];
    const float* bv = (const float*)d_in[6];
    const float* Wo = (const float*)d_in[7];
    const float* bo = (const float*)d_in[8];
    float* out = (float*)d_out;

    bf16 *wqh, *wql, *wkh, *wkl, *wvh, *wvl;
    float *woh, *wol;
    cudaGetSymbolAddress((void**)&wqh, g_Wqbh); cudaGetSymbolAddress((void**)&wql, g_Wqbl);
    cudaGetSymbolAddress((void**)&wkh, g_Wkbh); cudaGetSymbolAddress((void**)&wkl, g_Wkbl);
    cudaGetSymbolAddress((void**)&wvh, g_Wvbh); cudaGetSymbolAddress((void**)&wvl, g_Wvbl);
    cudaGetSymbolAddress((void**)&woh, g_Woh);  cudaGetSymbolAddress((void**)&wol, g_Wol);

    const int nw = DMM * DIN_;   // 131072
    split_w_bf16<<<nw/256, 256>>>(Wq, wqh, wql, nw);
    split_w_bf16<<<nw/256, 256>>>(Wk, wkh, wkl, nw);
    split_w_bf16<<<nw/256, 256>>>(Wv, wvh, wvl, nw);
    split_w_f32 <<<nw/256, 256>>>(Wo, woh, wol, nw);

    const int score_smem = 4 * 128 * SK_LD * (int)sizeof(bf16);   // 73,728 B
    cudaFuncSetAttribute(score_kernel, cudaFuncAttributeMaxDynamicSharedMemorySize, score_smem);

    qkv_kernel  <<<dim3(128, 4, 3), 256>>>(x, bq, bk, bv);
    score_kernel<<<dim3(16, 16, 32), 256, score_smem>>>(out);
    softpv_kernel<<<dim3(32, 32), 256>>>(out);
    oproj_kernel<<<dim3(64, 4), 256>>>(bo, out);
}

// round 15
// speedup vs baseline: 2.9749x; 1.1984x over previous
#include <cuda_runtime.h>
#include <cuda_bf16.h>
#include <mma.h>
#include <cstdint>

namespace wm = nvcuda::wmma;

#define BB   4
#define DIN_ 256
#define SS   2048
#define DMM  512
#define HH   8
#define DKK  64
#define NH   32                      // B*H
#define ZSIZE (BB*DIN_*SS)           // 2097152

typedef __nv_bfloat16 bf16;

// ---- device-global scratch (allocation-free rule) -------------------------
__device__ bf16  g_Qbh[NH*SS*DKK], g_Qbl[NH*SS*DKK];
__device__ bf16  g_Kbh[NH*SS*DKK], g_Kbl[NH*SS*DKK];
__device__ float g_V  [NH*SS*DKK];                      // tf32-rounded values
__device__ float g_AOh[SS*NH*DKK], g_AOl[SS*NH*DKK];    // flat [S][B*H][dk]
__device__ bf16  g_Wqbh[DMM*DIN_], g_Wqbl[DMM*DIN_];
__device__ bf16  g_Wkbh[DMM*DIN_], g_Wkbl[DMM*DIN_];
__device__ bf16  g_Wvbh[DMM*DIN_], g_Wvbl[DMM*DIN_];
__device__ float g_Woh[DIN_*DMM],  g_Wol[DIN_*DMM];

__device__ __forceinline__ float f2tf32(float x){
    float r; asm("cvt.rna.tf32.f32 %0, %1;" : "=f"(r) : "f"(x)); return r;
}

// bf16 fragments (m16n16k16)
using BFragA  = wm::fragment<wm::matrix_a,    16,16,16, bf16, wm::row_major>;
using BFragBc = wm::fragment<wm::matrix_b,    16,16,16, bf16, wm::col_major>;
using BFragC  = wm::fragment<wm::accumulator, 16,16,16, float>;
// tf32 fragments (m16n16k8)
using TFragA  = wm::fragment<wm::matrix_a,    16,16,8, wm::precision::tf32, wm::row_major>;
using TFragBc = wm::fragment<wm::matrix_b,    16,16,8, wm::precision::tf32, wm::col_major>;
using TFragBr = wm::fragment<wm::matrix_b,    16,16,8, wm::precision::tf32, wm::row_major>;
using TFragC  = wm::fragment<wm::accumulator, 16,16,8, float>;

// ---------------------------------------------------------------------------
// Kernel 0a/0b: weight splits.
// ---------------------------------------------------------------------------
__global__ void split_w_bf16(const float* __restrict__ s,
                             bf16* __restrict__ h, bf16* __restrict__ l, int n)
{
    int i = blockIdx.x * 256 + threadIdx.x;
    if (i < n){
        float v = s[i];
        bf16 hh = __float2bfloat16(v);
        h[i] = hh;
        l[i] = __float2bfloat16(v - __bfloat162float(hh));
    }
}
__global__ void split_w_f32(const float* __restrict__ s,
                            float* __restrict__ h, float* __restrict__ l, int n)
{
    int i = blockIdx.x * 256 + threadIdx.x;
    if (i < n){ float v = s[i]; float hh = f2tf32(v); h[i] = hh; l[i] = v - hh; }
}

// ---------------------------------------------------------------------------
// Kernel 1: QKV projections, bf16x2 (3-product) emulated fp32.
//   V now stored tf32-rounded (RNA) so PV can use it without cvt or lo-term.
// ---------------------------------------------------------------------------
__global__ void __launch_bounds__(256) qkv_kernel(
        const float* __restrict__ x,
        const float* __restrict__ bq, const float* __restrict__ bk,
        const float* __restrict__ bv)
{
    __shared__ __align__(16) char sraw[64*132*4];
    bf16*  shi  = (bf16*)sraw;
    bf16*  slo  = shi + 64*40;
    float* sC   = (float*)sraw;

    const int which = blockIdx.z;
    const bf16* Wh    = (which==0) ? g_Wqbh : (which==1 ? g_Wkbh : g_Wvbh);
    const bf16* Wl    = (which==0) ? g_Wqbl : (which==1 ? g_Wkbl : g_Wvbl);
    const float* bias = (which==0) ? bq    : (which==1 ? bk    : bv);

    const int r0 = blockIdx.x * 64;
    const int m0 = blockIdx.y * 128;
    const int s0 = r0 >> 2;
    const int t  = threadIdx.x;
    const int w  = t >> 5;
    const int wr = w >> 2;
    const int wc = w & 3;

    BFragC acc[2][2];
#pragma unroll
    for (int a=0;a<2;a++)
#pragma unroll
        for (int b2=0;b2<2;b2++) wm::fill_fragment(acc[a][b2], 0.0f);

    for (int kc = 0; kc < DIN_; kc += 32){
#pragma unroll
        for (int j = 0; j < 8; j++){
            int idx = j*256 + t;
            int sl  = idx & 15;
            int p   = idx >> 4;
            int bb  = p & 3;
            int il  = p >> 2;
            float v = x[bb*(DIN_*SS) + (kc+il)*SS + (s0+sl)];
            bf16 h  = __float2bfloat16(v);
            int pos = (sl*4 + bb)*40 + il;
            shi[pos] = h;
            slo[pos] = __float2bfloat16(v - __bfloat162float(h));
        }
        __syncthreads();

#pragma unroll
        for (int ks = 0; ks < 2; ks++){
            BFragA ahi[2], alo[2];
#pragma unroll
            for (int mt = 0; mt < 2; mt++){
                wm::load_matrix_sync(ahi[mt], shi + (wr*32 + mt*16)*40 + ks*16, 40);
                wm::load_matrix_sync(alo[mt], slo + (wr*32 + mt*16)*40 + ks*16, 40);
            }
#pragma unroll
            for (int nt = 0; nt < 2; nt++){
                BFragBc bhi, blo;
                const int wofs = (m0 + wc*32 + nt*16)*DIN_ + kc + ks*16;
                wm::load_matrix_sync(bhi, Wh + wofs, DIN_);
                wm::load_matrix_sync(blo, Wl + wofs, DIN_);
#pragma unroll
                for (int mt = 0; mt < 2; mt++){
                    wm::mma_sync(acc[mt][nt], ahi[mt], bhi, acc[mt][nt]);
                    wm::mma_sync(acc[mt][nt], ahi[mt], blo, acc[mt][nt]);
                    wm::mma_sync(acc[mt][nt], alo[mt], bhi, acc[mt][nt]);
                }
            }
        }
        __syncthreads();
    }

#pragma unroll
    for (int mt = 0; mt < 2; mt++)
#pragma unroll
        for (int nt = 0; nt < 2; nt++)
            wm::store_matrix_sync(sC + (wr*32 + mt*16)*132 + wc*32 + nt*16,
                                  acc[mt][nt], 132, wm::mem_row_major);
    __syncthreads();

#pragma unroll
    for (int it = 0; it < 32; it++){
        int rl = it*2 + (t >> 7);
        int ml = t & 127;
        int m  = m0 + ml;
        float v = sC[rl*132 + ml] + bias[m];
        int s  = s0 + (rl >> 2);
        int bb = rl & 3;
        int h  = m >> 6;
        int d  = m & 63;
        size_t o = (size_t)((bb*HH + h)*SS + s)*DKK + d;
        if (which == 2){
            g_V[o] = f2tf32(v);           // tf32-exact V for 1-term PV
        } else {
            bf16 hh = __float2bfloat16(v);
            bf16 ll = __float2bfloat16(v - __bfloat162float(hh));
            if (which == 0){ g_Qbh[o] = hh; g_Qbl[o] = ll; }
            else           { g_Kbh[o] = hh; g_Kbl[o] = ll; }
        }
    }
}

// ---------------------------------------------------------------------------
// Kernel 2a: scores = Q K^T (bf16x2, 3 MMA/k16).  (R13 wmma version, proven)
// CTA tile 128q x 128k, 8 warps.  grid (16,16,32), 72KB dyn smem, 2 CTA/SM.
// ---------------------------------------------------------------------------
#define SK_LD 72
__global__ void __launch_bounds__(256, 2) score_kernel(float* __restrict__ d_out)
{
    extern __shared__ __align__(16) bf16 sks[];
    bf16* sQh = sks;                    // [128][72]
    bf16* sQl = sQh + 128*SK_LD;
    bf16* sKh = sQl + 128*SK_LD;
    bf16* sKl = sKh + 128*SK_LD;

    const int q0 = blockIdx.x * 128;
    const int k0 = blockIdx.y * 128;
    const int n  = blockIdx.z;
    const int t  = threadIdx.x;
    const int w  = t >> 5;
    const int wr = w >> 2;              // 0..1 -> 4 m-tiles each
    const int wc = w & 3;               // 0..3 -> 2 n-tiles each

    const bf16* Qhg = g_Qbh + ((size_t)n*SS + q0)*DKK;
    const bf16* Qlg = g_Qbl + ((size_t)n*SS + q0)*DKK;
    const bf16* Khg = g_Kbh + ((size_t)n*SS + k0)*DKK;
    const bf16* Klg = g_Kbl + ((size_t)n*SS + k0)*DKK;

    // stage Q and K tiles: 128 rows x 8 uint4 (64 bf16) per array = 1024 uint4
#pragma unroll
    for (int i = 0; i < 4; i++){
        int idx = i*256 + t;            // 0..1023
        int r = idx >> 3, j = idx & 7;
        *(uint4*)(sQh + r*SK_LD + j*8) = *(const uint4*)(Qhg + r*DKK + j*8);
        *(uint4*)(sQl + r*SK_LD + j*8) = *(const uint4*)(Qlg + r*DKK + j*8);
        *(uint4*)(sKh + r*SK_LD + j*8) = *(const uint4*)(Khg + r*DKK + j*8);
        *(uint4*)(sKl + r*SK_LD + j*8) = *(const uint4*)(Klg + r*DKK + j*8);
    }
    __syncthreads();

    BFragC acc[4][2];
#pragma unroll
    for (int i=0;i<4;i++)
#pragma unroll
        for (int j=0;j<2;j++) wm::fill_fragment(acc[i][j], 0.0f);

#pragma unroll
    for (int ks = 0; ks < 4; ks++){
#pragma unroll
        for (int j = 0; j < 2; j++){
            const int ntr = (wc*2 + j)*16;
            BFragBc bh, bl;
            wm::load_matrix_sync(bh, sKh + ntr*SK_LD + ks*16, SK_LD);
            wm::load_matrix_sync(bl, sKl + ntr*SK_LD + ks*16, SK_LD);
#pragma unroll
            for (int i = 0; i < 4; i++){
                const int mtr = (wr*4 + i)*16;
                BFragA ah, al;
                wm::load_matrix_sync(ah, sQh + mtr*SK_LD + ks*16, SK_LD);
                wm::load_matrix_sync(al, sQl + mtr*SK_LD + ks*16, SK_LD);
                wm::mma_sync(acc[i][j], ah, bh, acc[i][j]);
                wm::mma_sync(acc[i][j], ah, bl, acc[i][j]);
                wm::mma_sync(acc[i][j], al, bh, acc[i][j]);
            }
        }
    }

    float* sco = d_out + (size_t)ZSIZE + (size_t)n*SS*SS;
#pragma unroll
    for (int i = 0; i < 4; i++)
#pragma unroll
        for (int j = 0; j < 2; j++)
            wm::store_matrix_sync(sco + (size_t)(q0 + (wr*4+i)*16)*SS + k0 + (wc*2+j)*16,
                                  acc[i][j], SS, wm::mem_row_major);
}

// ---------------------------------------------------------------------------
// Kernel 2b: fused softmax + PV.  CTA = (head n, 128 q-rows), 256 threads.
//   Phase 1: warp w -> softmax rows w*16..w*16+15, in-place normalize attn_w.
//   Phase 2: warp w = m-tile (same 16 rows), acc[4] over 64 d-cols.
//            P rounded RNA-tf32 at fragment load; V already tf32 -> 1 MMA/k8.
// grid (16 q-tiles, 32 heads), 36KB static smem, ~6 CTA/SM.
// ---------------------------------------------------------------------------
__global__ void __launch_bounds__(256) softpv_kernel(float* __restrict__ d_out)
{
    __shared__ __align__(16) float vst[128*SK_LD];     // V stage / AO stage

    const int q0   = blockIdx.x * 128;
    const int n    = blockIdx.y;
    const int t    = threadIdx.x;
    const int w    = t >> 5;            // 0..7
    const int lane = t & 31;

    float* attw = d_out + (size_t)ZSIZE + (size_t)n*SS*SS + (size_t)q0*SS;

    // ---- Phase 1: warp w -> softmax rows w*16 .. w*16+15 (in registers)
    for (int rr = 0; rr < 16; rr++){
        float4* row4 = (float4*)(attw + (size_t)(w*16 + rr)*SS);
        float4 v[16];
        float m = -3.4e38f;
#pragma unroll
        for (int c = 0; c < 16; c++){
            v[c] = row4[lane + 32*c];
            m = fmaxf(m, fmaxf(fmaxf(v[c].x, v[c].y), fmaxf(v[c].z, v[c].w)));
        }
#pragma unroll
        for (int o = 16; o > 0; o >>= 1) m = fmaxf(m, __shfl_xor_sync(0xffffffffu, m, o));
        float sum = 0.f;
#pragma unroll
        for (int c = 0; c < 16; c++){
            v[c].x = __expf(v[c].x - m); v[c].y = __expf(v[c].y - m);
            v[c].z = __expf(v[c].z - m); v[c].w = __expf(v[c].w - m);
            sum += (v[c].x + v[c].y) + (v[c].z + v[c].w);
        }
#pragma unroll
        for (int o = 16; o > 0; o >>= 1) sum += __shfl_xor_sync(0xffffffffu, sum, o);
        float inv = 1.0f / sum;
#pragma unroll
        for (int c = 0; c < 16; c++){
            float4 e = v[c];
            row4[lane + 32*c] = make_float4(e.x*inv, e.y*inv, e.z*inv, e.w*inv);
        }
    }
    __syncthreads();   // block-wide visibility of this CTA's 128 attn_w rows

    // ---- Phase 2: PV.  warp w -> m-tile rows w*16..w*16+15, acc over 64 cols
    const float* Vg = g_V + (size_t)n*SS*DKK;

    TFragC acc[4];
#pragma unroll
    for (int j = 0; j < 4; j++) wm::fill_fragment(acc[j], 0.0f);

    for (int kb = 0; kb < 16; kb++){
        const float* src = Vg + (size_t)kb*128*DKK;
#pragma unroll
        for (int i = 0; i < 8; i++){
            int idx = i*256 + t;        // 0..2047 float4 (128 rows x 16 float4)
            int r = idx >> 4, j = idx & 15;
            *(uint4*)(vst + r*SK_LD + j*4) = *(const uint4*)(src + r*DKK + j*4);
        }
        __syncthreads();

#pragma unroll
        for (int ks = 0; ks < 16; ks++){
            TFragA p;
            wm::load_matrix_sync(p, attw + (size_t)(w*16)*SS + kb*128 + ks*8, SS);
#pragma unroll
            for (int e = 0; e < p.num_elements; e++) p.x[e] = f2tf32(p.x[e]);
#pragma unroll
            for (int j = 0; j < 4; j++){
                TFragBr vr;                       // V already tf32-exact
                wm::load_matrix_sync(vr, vst + (ks*8)*SK_LD + j*16, SK_LD);
                wm::mma_sync(acc[j], p, vr, acc[j]);
            }
        }
        __syncthreads();
    }

    // epilogue: stage AO [128][68] in smem, split to tf32 hi/lo, store flat
#pragma unroll
    for (int j = 0; j < 4; j++)
        wm::store_matrix_sync(vst + (w*16)*68 + j*16, acc[j], 68, wm::mem_row_major);
    __syncthreads();

#pragma unroll
    for (int i = 0; i < 32; i++){
        int idx = i*256 + t;            // 0..8191
        int q = idx >> 6, d = idx & 63;
        float vv = vst[q*68 + d];
        float hh = f2tf32(vv);
        size_t o = (size_t)(q0 + q)*(NH*DKK) + (size_t)n*DKK + d;
        g_AOh[o] = hh;
        g_AOl[o] = vv - hh;
    }
}

// ---------------------------------------------------------------------------
// Kernel 3: out-projection + transpose store (tf32 split-3).  (unchanged)
// ---------------------------------------------------------------------------
__global__ void __launch_bounds__(256) oproj_kernel(
        const float* __restrict__ bo, float* __restrict__ d_out)
{
    __shared__ __align__(128) float sbuf[64*132];

    const int r0 = blockIdx.x * 128;
    const int e0 = blockIdx.y * 64;
    const int t  = threadIdx.x;
    const int w  = t >> 5;
    const int wr = w >> 1;
    const int wc = w & 1;

    TFragC acc[2][2];
#pragma unroll
    for (int a=0;a<2;a++)
#pragma unroll
        for (int b2=0;b2<2;b2++) wm::fill_fragment(acc[a][b2], 0.0f);

    for (int ks = 0; ks < 64; ks++){
        TFragA ahi[2], alo[2];
#pragma unroll
        for (int mt = 0; mt < 2; mt++){
            size_t aofs = (size_t)(r0 + wr*32 + mt*16)*DMM + ks*8;
            wm::load_matrix_sync(ahi[mt], g_AOh + aofs, DMM);
            wm::load_matrix_sync(alo[mt], g_AOl + aofs, DMM);
        }
#pragma unroll
        for (int nt = 0; nt < 2; nt++){
            TFragBc bhi, blo;
            const int wofs = (e0 + wc*32 + nt*16)*DMM + ks*8;
            wm::load_matrix_sync(bhi, g_Woh + wofs, DMM);
            wm::load_matrix_sync(blo, g_Wol + wofs, DMM);
#pragma unroll
            for (int mt = 0; mt < 2; mt++){
                wm::mma_sync(acc[mt][nt], ahi[mt], bhi, acc[mt][nt]);
                wm::mma_sync(acc[mt][nt], ahi[mt], blo, acc[mt][nt]);
                wm::mma_sync(acc[mt][nt], alo[mt], bhi, acc[mt][nt]);
            }
        }
    }

#pragma unroll
    for (int mt = 0; mt < 2; mt++)
#pragma unroll
        for (int nt = 0; nt < 2; nt++)
            wm::store_matrix_sync(sbuf + (wc*32 + nt*16)*132 + wr*32 + mt*16,
                                  acc[mt][nt], 132, wm::mem_col_major);
    __syncthreads();

    const int b  = r0 >> 11;
    const int s0 = r0 & 2047;
#pragma unroll
    for (int it = 0; it < 32; it++){
        int el = it*2 + (t >> 7);
        int sl = t & 127;
        float v = sbuf[el*132 + sl] + bo[e0 + el];
        d_out[(size_t)b*(DIN_*SS) + (size_t)(e0 + el)*SS + s0 + sl] = v;
    }
}

// ---------------------------------------------------------------------------
extern "C" void kernel_launch(void* const* d_in, const int* in_sizes, int n_in,
                              void* d_out, int out_size)
{
    const float* x  = (const float*)d_in[0];
    const float* Wq = (const float*)d_in[1];
    const float* bq = (const float*)d_in[2];
    const float* Wk = (const float*)d_in[3];
    const float* bk = (const float*)d_in[4];
    const float* Wv = (const float*)d_in[5];
    const float* bv = (const float*)d_in[6];
    const float* Wo = (const float*)d_in[7];
    const float* bo = (const float*)d_in[8];
    float* out = (float*)d_out;

    bf16 *wqh, *wql, *wkh, *wkl, *wvh, *wvl;
    float *woh, *wol;
    cudaGetSymbolAddress((void**)&wqh, g_Wqbh); cudaGetSymbolAddress((void**)&wql, g_Wqbl);
    cudaGetSymbolAddress((void**)&wkh, g_Wkbh); cudaGetSymbolAddress((void**)&wkl, g_Wkbl);
    cudaGetSymbolAddress((void**)&wvh, g_Wvbh); cudaGetSymbolAddress((void**)&wvl, g_Wvbl);
    cudaGetSymbolAddress((void**)&woh, g_Woh);  cudaGetSymbolAddress((void**)&wol, g_Wol);

    const int nw = DMM * DIN_;   // 131072
    split_w_bf16<<<nw/256, 256>>>(Wq, wqh, wql, nw);
    split_w_bf16<<<nw/256, 256>>>(Wk, wkh, wkl, nw);
    split_w_bf16<<<nw/256, 256>>>(Wv, wvh, wvl, nw);
    split_w_f32 <<<nw/256, 256>>>(Wo, woh, wol, nw);

    const int score_smem = 4 * 128 * SK_LD * (int)sizeof(bf16);   // 73,728 B
    cudaFuncSetAttribute(score_kernel, cudaFuncAttributeMaxDynamicSharedMemorySize, score_smem);

    qkv_kernel   <<<dim3(128, 4, 3), 256>>>(x, bq, bk, bv);
    score_kernel <<<dim3(16, 16, 32), 256, score_smem>>>(out);
    softpv_kernel<<<dim3(16, 32), 256>>>(out);
    oproj_kernel <<<dim3(64, 4), 256>>>(bo, out);
}